// round 16
// baseline (speedup 1.0000x reference)
#include <cuda_runtime.h>
#include <cuda_fp16.h>
#include <cstdint>

// Problem dims (fixed by the reference)
#define BB   2
#define SS   1024
#define DD   1024
#define HH   2048
#define EE   8
#define KK   2
#define NPAIR (BB*SS*KK)   // 4096 (token, k-slot) pairs
#define MAXR  NPAIR

// ---------------- scratch (static device globals; no allocation) -------------
// Referenced ONLY inside device code (never passed as kernel args from host).
__device__ int   g_cnt[EE];
__device__ int   g_tok [EE * MAXR];
__device__ int   g_pair[EE * MAXR];
__device__ __half g_xh[(size_t)BB * SS * DD];
__device__ __half g_kh[(size_t)EE * HH * DD];
__device__ __half g_vh[(size_t)EE * DD * HH];
__device__ __half g_hid[(size_t)NPAIR * HH];

// ---------------- PTX helpers (sm_80-class only) ------------------------------
__device__ __forceinline__ uint32_t smem_u32(const void* p) {
    uint32_t a;
    asm("{ .reg .u64 t; cvta.to.shared.u64 t, %1; cvt.u32.u64 %0, t; }" : "=r"(a) : "l"(p));
    return a;
}
__device__ __forceinline__ void cp_async16(uint32_t dst, const void* src, bool valid) {
    int sz = valid ? 16 : 0;
    asm volatile("cp.async.cg.shared.global [%0], [%1], 16, %2;" :: "r"(dst), "l"(src), "r"(sz) : "memory");
}
#define CP_COMMIT() asm volatile("cp.async.commit_group;" ::: "memory")
#define CP_WAIT(N)  asm volatile("cp.async.wait_group %0;" :: "n"(N) : "memory")

__device__ __forceinline__ void ldsm4(uint32_t (&r)[4], uint32_t addr) {
    asm volatile("ldmatrix.sync.aligned.m8n8.x4.shared.b16 {%0,%1,%2,%3}, [%4];"
                 : "=r"(r[0]), "=r"(r[1]), "=r"(r[2]), "=r"(r[3]) : "r"(addr));
}
// fp16-accumulate MMA with C = 0: d(fp16x2 x2) = a*b. Runs at the full HMMA
// rate if fp32-acc is the half-rate variant (the round-16 hypothesis).
__device__ __forceinline__ void mma16816_f16c0(uint32_t& d0, uint32_t& d1,
                                               const uint32_t (&a)[4],
                                               uint32_t b0, uint32_t b1) {
    asm volatile(
        "{\n\t.reg .b32 z;\n\tmov.b32 z, 0;\n\t"
        "mma.sync.aligned.m16n8k16.row.col.f16.f16.f16.f16 "
        "{%0,%1}, {%2,%3,%4,%5}, {%6,%7}, {z,z};\n\t}"
        : "=r"(d0), "=r"(d1)
        : "r"(a[0]), "r"(a[1]), "r"(a[2]), "r"(a[3]), "r"(b0), "r"(b1));
}
__device__ __forceinline__ uint32_t sw128(uint32_t off) { return off ^ ((off >> 3) & 0x70); }

// ---------------- small kernels ----------------------------------------------
__global__ void zero_cnt_kernel() { if (threadIdx.x < EE) g_cnt[threadIdx.x] = 0; }

__device__ __forceinline__ float gelu_tanh(float v) {
    const float c = 0.7978845608028654f;
    float t = tanhf(c * (v + 0.044715f * v * v * v));
    return 0.5f * v * (1.0f + t);
}

// ONE streaming pass: fp32->fp16 for x, keys, values; zero-init out;
// PLUS one dedicated trailing block that buckets the (token,k) pairs by expert.
__device__ __forceinline__ uint32_t pack_h2(float a, float b) {
    __half2 h = __floats2half2_rn(a, b);
    return *reinterpret_cast<uint32_t*>(&h);
}
__global__ void cvt_all_kernel(const float* __restrict__ x,
                               const float* __restrict__ keys,
                               const float* __restrict__ values,
                               float* __restrict__ out,
                               const int* __restrict__ eidx) {
    // Trailing block: bucket work (g_cnt pre-zeroed by zero_cnt_kernel).
    if (blockIdx.x == gridDim.x - 1) {
#pragma unroll
        for (int s = 0; s < NPAIR / 512; s++) {
            int p = threadIdx.x + s * 512;
            int token = p / KK;
            int e = eidx[p];
            int pos = atomicAdd(&g_cnt[e], 1);
            g_tok [e * MAXR + pos] = token;
            g_pair[e * MAXR + pos] = p;
        }
        return;
    }

    const int XN8 = BB * SS * DD / 8;
    const int KN8 = EE * HH * DD / 8;
    const int VN8 = EE * DD * HH / 8;
    const int ON8 = BB * SS * DD / 8;
    int i = blockIdx.x * blockDim.x + threadIdx.x;
    const float4* src; __half* dst; int j;
    if (i < XN8)                  { src = (const float4*)x;      dst = g_xh; j = i; }
    else if (i < XN8+KN8)         { src = (const float4*)keys;   dst = g_kh; j = i - XN8; }
    else if (i < XN8+KN8+VN8)     { src = (const float4*)values; dst = g_vh; j = i - XN8 - KN8; }
    else if (i < XN8+KN8+VN8+ON8) {
        int k = i - XN8 - KN8 - VN8;
        float4 z = make_float4(0.f, 0.f, 0.f, 0.f);
        reinterpret_cast<float4*>(out)[2*k]   = z;
        reinterpret_cast<float4*>(out)[2*k+1] = z;
        return;
    } else return;
    float4 v0 = __ldcs(src + 2*j);
    float4 v1 = __ldcs(src + 2*j + 1);
    uint4 o;
    o.x = pack_h2(v0.x, v0.y);
    o.y = pack_h2(v0.z, v0.w);
    o.z = pack_h2(v1.x, v1.y);
    o.w = pack_h2(v1.z, v1.w);
    reinterpret_cast<uint4*>(dst)[j] = o;
}

// ================= GEMM1: 8-warp, 256 threads, warp tile 32x64 ================
// hidden[pair] = gelu(x[token] @ keys[e]^T), fp16 out.
// MMA: fp16-acc C=0 per k16 step, promoted into fp32 accumulators.
#define A_TILE_B 16384
#define B_TILE_B 16384
#define STAGE_B  (A_TILE_B + B_TILE_B) // 32 KB
#define NSTAGE   3
#define SMEM_REQ (NSTAGE * STAGE_B)    // 96 KB

__global__ void __launch_bounds__(256, 2) moe_gemm1_kernel() {
    const int tid = threadIdx.x;

    const int e      = blockIdx.z;
    const int n_rows = g_cnt[e];
    const int row0   = blockIdx.y * 128;
    if (row0 >= n_rows) return;
    const int col0   = blockIdx.x * 128;

    const int* gat = g_tok  + e * MAXR;
    const int* pr  = g_pair + e * MAXR;
    const __half* A = g_xh;
    const __half* B = g_kh + (size_t)e * HH * DD;

    extern __shared__ char smem_dyn[];
    const uint32_t smB = smem_u32(smem_dyn);

    const int wid  = tid >> 5, lane = tid & 31;
    const int wm   = wid & 3;
    const int wn   = wid >> 2;

    const int c8    = tid & 7;
    const int rbase = tid >> 3;        // 0..31
    bool aok[4]; int aid[4]; uint32_t adst[4];
    int brow[4];  uint32_t bdst[4];
#pragma unroll
    for (int s = 0; s < 4; s++) {
        int r = rbase + 32 * s;
        uint32_t sw = sw128((uint32_t)(r * 128 + c8 * 16));
        adst[s] = sw;
        bdst[s] = A_TILE_B + sw;
        int grow = row0 + r;
        aok[s] = grow < n_rows;
        aid[s] = aok[s] ? gat[grow] : 0;
        brow[s] = col0 + r;
    }

    auto issue = [&](int stage, int buf) {
        size_t k0 = (size_t)stage * 64 + c8 * 8;
        uint32_t b = smB + (uint32_t)buf * STAGE_B;
#pragma unroll
        for (int s = 0; s < 4; s++)
            cp_async16(b + adst[s], A + (size_t)aid[s] * DD + k0, aok[s]);
#pragma unroll
        for (int s = 0; s < 4; s++)
            cp_async16(b + bdst[s], B + (size_t)brow[s] * DD + k0, true);
        CP_COMMIT();
    };

    float acc[2][8][4];
#pragma unroll
    for (int mt = 0; mt < 2; mt++)
#pragma unroll
        for (int nt = 0; nt < 8; nt++)
#pragma unroll
            for (int r = 0; r < 4; r++) acc[mt][nt][r] = 0.0f;

    const int aRowL  = wm * 32 + (lane & 15);
    const int aKHalf = (lane >> 4) * 16;
    const int bRowL  = wn * 64 + ((lane >> 4) << 3) + (lane & 7);
    const int bKHalf = ((lane >> 3) & 1) * 16;

    uint32_t ah[2][2][4], bh[2][4][4];

    auto load_frags = [&](int fb, uint32_t sA, uint32_t sB, int ks) {
        const int kb = ks * 32;
#pragma unroll
        for (int mt = 0; mt < 2; mt++)
            ldsm4(ah[fb][mt], sA + sw128((uint32_t)((aRowL + mt*16) * 128 + kb + aKHalf)));
#pragma unroll
        for (int ng = 0; ng < 4; ng++)
            ldsm4(bh[fb][ng], sB + sw128((uint32_t)((bRowL + ng*16) * 128 + kb + bKHalf)));
    };
    auto do_mma = [&](int fb) {
#pragma unroll
        for (int mt = 0; mt < 2; mt++)
#pragma unroll
            for (int nt = 0; nt < 8; nt++) {
                const int ng = nt >> 1, h = (nt & 1) * 2;
                uint32_t d0, d1;
                mma16816_f16c0(d0, d1, ah[fb][mt], bh[fb][ng][h], bh[fb][ng][h+1]);
                float2 f0 = __half22float2(*reinterpret_cast<__half2*>(&d0));
                float2 f1 = __half22float2(*reinterpret_cast<__half2*>(&d1));
                acc[mt][nt][0] += f0.x;
                acc[mt][nt][1] += f0.y;
                acc[mt][nt][2] += f1.x;
                acc[mt][nt][3] += f1.y;
            }
    };

    const int NS = DD / 64;
    issue(0, 0);
    issue(1, 1);

    for (int i = 0; i < NS; i++) {
        const int buf = i % NSTAGE;
        if (i + 1 < NS) { CP_WAIT(1); } else { CP_WAIT(0); }
        __syncthreads();
        if (i + 2 < NS) issue(i + 2, (i + 2) % NSTAGE);

        const uint32_t bb = smB + (uint32_t)buf * STAGE_B;
        const uint32_t sA = bb, sB = bb + A_TILE_B;

        load_frags(0, sA, sB, 0);
#pragma unroll
        for (int ks = 0; ks < 4; ks++) {
            if (ks < 3) load_frags((ks + 1) & 1, sA, sB, ks + 1);
            do_mma(ks & 1);
        }
    }

    int prid[2][2];
#pragma unroll
    for (int mt = 0; mt < 2; mt++)
#pragma unroll
        for (int hf = 0; hf < 2; hf++) {
            int grow = row0 + wm*32 + mt*16 + (lane >> 2) + hf*8;
            prid[mt][hf] = (grow < n_rows) ? pr[grow] : -1;
        }

#pragma unroll
    for (int mt = 0; mt < 2; mt++)
#pragma unroll
        for (int hf = 0; hf < 2; hf++) {
            const int pid = prid[mt][hf];
            if (pid < 0) continue;
#pragma unroll
            for (int nt = 0; nt < 8; nt++) {
                const int colg = col0 + wn*64 + nt*8 + (lane & 3)*2;
                float v0 = gelu_tanh(acc[mt][nt][hf*2 + 0]);
                float v1 = gelu_tanh(acc[mt][nt][hf*2 + 1]);
                *reinterpret_cast<__half2*>(g_hid + (size_t)pid * HH + colg) =
                    __floats2half2_rn(v0, v1);
            }
        }
}

// ================= GEMM2: 4-warp, 128 threads, warp tile 64x64 ================
// out[token] += ew[pair] * (hidden[pair] @ values[e]^T), atomicAdd epilogue.
// MMA: fp16-acc C=0 per k16 step, promoted into fp32 accumulators.
__global__ void __launch_bounds__(128, 2) moe_gemm2_kernel(const float* __restrict__ ew,
                                                           float* __restrict__ out) {
    const int tid = threadIdx.x;

    const int e      = blockIdx.z;
    const int n_rows = g_cnt[e];
    const int row0   = blockIdx.y * 128;
    if (row0 >= n_rows) return;
    const int col0   = blockIdx.x * 128;

    const int* pr  = g_pair + e * MAXR;
    const __half* A = g_hid;
    const __half* B = g_vh + (size_t)e * DD * HH;

    extern __shared__ char smem_dyn[];
    const uint32_t smB = smem_u32(smem_dyn);

    const int wid  = tid >> 5, lane = tid & 31;
    const int wm   = wid & 1;
    const int wn   = wid >> 1;

    const int c8    = tid & 7;
    const int rbase = tid >> 3;        // 0..15
    bool aok[8]; int aid[8]; uint32_t adst[8];
    int brow[8];  uint32_t bdst[8];
#pragma unroll
    for (int s = 0; s < 8; s++) {
        int r = rbase + 16 * s;
        uint32_t sw = sw128((uint32_t)(r * 128 + c8 * 16));
        adst[s] = sw;
        bdst[s] = A_TILE_B + sw;
        int grow = row0 + r;
        aok[s] = grow < n_rows;
        aid[s] = aok[s] ? pr[grow] : 0;
        brow[s] = col0 + r;
    }

    auto issue = [&](int stage, int buf) {
        size_t k0 = (size_t)stage * 64 + c8 * 8;
        uint32_t b = smB + (uint32_t)buf * STAGE_B;
#pragma unroll
        for (int s = 0; s < 8; s++)
            cp_async16(b + adst[s], A + (size_t)aid[s] * HH + k0, aok[s]);
#pragma unroll
        for (int s = 0; s < 8; s++)
            cp_async16(b + bdst[s], B + (size_t)brow[s] * HH + k0, true);
        CP_COMMIT();
    };

    float acc[4][8][4];
#pragma unroll
    for (int mt = 0; mt < 4; mt++)
#pragma unroll
        for (int nt = 0; nt < 8; nt++)
#pragma unroll
            for (int r = 0; r < 4; r++) acc[mt][nt][r] = 0.0f;

    const int aRowL  = wm * 64 + (lane & 15);
    const int aKHalf = (lane >> 4) * 16;
    const int bRowL  = wn * 64 + ((lane >> 4) << 3) + (lane & 7);
    const int bKHalf = ((lane >> 3) & 1) * 16;

    uint32_t ah[2][4][4], bh[2][4][4];

    auto load_frags = [&](int fb, uint32_t sA, uint32_t sB, int ks) {
        const int kb = ks * 32;
#pragma unroll
        for (int mt = 0; mt < 4; mt++)
            ldsm4(ah[fb][mt], sA + sw128((uint32_t)((aRowL + mt*16) * 128 + kb + aKHalf)));
#pragma unroll
        for (int ng = 0; ng < 4; ng++)
            ldsm4(bh[fb][ng], sB + sw128((uint32_t)((bRowL + ng*16) * 128 + kb + bKHalf)));
    };
    auto do_mma = [&](int fb) {
#pragma unroll
        for (int mt = 0; mt < 4; mt++)
#pragma unroll
            for (int nt = 0; nt < 8; nt++) {
                const int ng = nt >> 1, h = (nt & 1) * 2;
                uint32_t d0, d1;
                mma16816_f16c0(d0, d1, ah[fb][mt], bh[fb][ng][h], bh[fb][ng][h+1]);
                float2 f0 = __half22float2(*reinterpret_cast<__half2*>(&d0));
                float2 f1 = __half22float2(*reinterpret_cast<__half2*>(&d1));
                acc[mt][nt][0] += f0.x;
                acc[mt][nt][1] += f0.y;
                acc[mt][nt][2] += f1.x;
                acc[mt][nt][3] += f1.y;
            }
    };

    const int NS = HH / 64;
    issue(0, 0);
    issue(1, 1);

    for (int i = 0; i < NS; i++) {
        const int buf = i % NSTAGE;
        if (i + 1 < NS) { CP_WAIT(1); } else { CP_WAIT(0); }
        __syncthreads();
        if (i + 2 < NS) issue(i + 2, (i + 2) % NSTAGE);

        const uint32_t bb = smB + (uint32_t)buf * STAGE_B;
        const uint32_t sA = bb, sB = bb + A_TILE_B;

        load_frags(0, sA, sB, 0);
#pragma unroll
        for (int ks = 0; ks < 4; ks++) {
            if (ks < 3) load_frags((ks + 1) & 1, sA, sB, ks + 1);
            do_mma(ks & 1);
        }
    }

    int   prid[4][2];
    float wgt [4][2];
#pragma unroll
    for (int mt = 0; mt < 4; mt++)
#pragma unroll
        for (int hf = 0; hf < 2; hf++) {
            int grow = row0 + wm*64 + mt*16 + (lane >> 2) + hf*8;
            prid[mt][hf] = (grow < n_rows) ? pr[grow] : -1;
            wgt [mt][hf] = (prid[mt][hf] >= 0) ? ew[prid[mt][hf]] : 1.0f;
        }

#pragma unroll
    for (int mt = 0; mt < 4; mt++)
#pragma unroll
        for (int hf = 0; hf < 2; hf++) {
            const int pid = prid[mt][hf];
            if (pid < 0) continue;
            const float w = wgt[mt][hf];
#pragma unroll
            for (int nt = 0; nt < 8; nt++) {
                const int colg = col0 + wn*64 + nt*8 + (lane & 3)*2;
                // out[token, colg] += w * v ; exactly 2 commutative adds per
                // element across the kernel -> deterministic.
                float* dst = out + (size_t)(pid >> 1) * DD + colg;
                atomicAdd(dst + 0, w * acc[mt][nt][hf*2 + 0]);
                atomicAdd(dst + 1, w * acc[mt][nt][hf*2 + 1]);
            }
        }
}

// ---------------- entry point ---------------------------------------------------
extern "C" void kernel_launch(void* const* d_in, const int* in_sizes, int n_in,
                              void* d_out, int out_size) {
    const float* x      = (const float*)d_in[0];   // [B,S,D]
    const float* keys   = (const float*)d_in[1];   // [E,H,D]
    const float* values = (const float*)d_in[2];   // [E,D,H]
    const int*   eidx   = (const int*)  d_in[3];   // [B,S,K]
    const float* ew     = (const float*)d_in[4];   // [B,S,K]
    float* out = (float*)d_out;                    // [B,S,D]

    cudaFuncSetAttribute((const void*)moe_gemm1_kernel,
                         cudaFuncAttributeMaxDynamicSharedMemorySize, SMEM_REQ);
    cudaFuncSetAttribute((const void*)moe_gemm2_kernel,
                         cudaFuncAttributeMaxDynamicSharedMemorySize, SMEM_REQ);

    zero_cnt_kernel<<<1, 32>>>();

    const int TOT8 = (BB*SS*DD + EE*HH*DD + EE*DD*HH + BB*SS*DD) / 8;
    const int nblk = (TOT8 + 511) / 512 + 1;   // +1 trailing bucket block
    cvt_all_kernel<<<nblk, 512>>>(x, keys, values, out, eidx);

    dim3 g1(HH / 128, MAXR / 128, EE);   // (16, 32, 8)
    moe_gemm1_kernel<<<g1, 256, SMEM_REQ>>>();

    dim3 g2(DD / 128, MAXR / 128, EE);   // (8, 32, 8)
    moe_gemm2_kernel<<<g2, 128, SMEM_REQ>>>(ew, out);
}

// round 17
// speedup vs baseline: 1.5370x; 1.5370x over previous
#include <cuda_runtime.h>
#include <cuda_fp16.h>
#include <cstdint>

// Problem dims (fixed by the reference)
#define BB   2
#define SS   1024
#define DD   1024
#define HH   2048
#define EE   8
#define KK   2
#define NPAIR (BB*SS*KK)   // 4096 (token, k-slot) pairs
#define MAXR  NPAIR
#define NTILE_MAX 39       // sum_e ceil(cnt_e/128) <= 4096/128 + (EE-1) = 39

// ---------------- scratch (static device globals; no allocation) -------------
// Referenced ONLY inside device code (never passed as kernel args from host).
__device__ int   g_cnt[EE];
__device__ int   g_tok [EE * MAXR];
__device__ int   g_pair[EE * MAXR];
__device__ int   g_tiles[NTILE_MAX];   // (e << 16) | row_tile
__device__ int   g_ntiles;
__device__ __half g_xh[(size_t)BB * SS * DD];
__device__ __half g_kh[(size_t)EE * HH * DD];
__device__ __half g_vh[(size_t)EE * DD * HH];
__device__ __half g_hid[(size_t)NPAIR * HH];

// ---------------- PTX helpers (sm_80-class only) ------------------------------
__device__ __forceinline__ uint32_t smem_u32(const void* p) {
    uint32_t a;
    asm("{ .reg .u64 t; cvta.to.shared.u64 t, %1; cvt.u32.u64 %0, t; }" : "=r"(a) : "l"(p));
    return a;
}
__device__ __forceinline__ void cp_async16(uint32_t dst, const void* src, bool valid) {
    int sz = valid ? 16 : 0;
    asm volatile("cp.async.cg.shared.global [%0], [%1], 16, %2;" :: "r"(dst), "l"(src), "r"(sz) : "memory");
}
#define CP_COMMIT() asm volatile("cp.async.commit_group;" ::: "memory")
#define CP_WAIT(N)  asm volatile("cp.async.wait_group %0;" :: "n"(N) : "memory")

__device__ __forceinline__ void ldsm4(uint32_t (&r)[4], uint32_t addr) {
    asm volatile("ldmatrix.sync.aligned.m8n8.x4.shared.b16 {%0,%1,%2,%3}, [%4];"
                 : "=r"(r[0]), "=r"(r[1]), "=r"(r[2]), "=r"(r[3]) : "r"(addr));
}
__device__ __forceinline__ void mma16816(float (&d)[4], const uint32_t (&a)[4],
                                         uint32_t b0, uint32_t b1) {
    asm volatile(
        "mma.sync.aligned.m16n8k16.row.col.f32.f16.f16.f32 "
        "{%0,%1,%2,%3}, {%4,%5,%6,%7}, {%8,%9}, {%0,%1,%2,%3};"
        : "+f"(d[0]), "+f"(d[1]), "+f"(d[2]), "+f"(d[3])
        : "r"(a[0]), "r"(a[1]), "r"(a[2]), "r"(a[3]), "r"(b0), "r"(b1));
}
__device__ __forceinline__ uint32_t sw128(uint32_t off) { return off ^ ((off >> 3) & 0x70); }

__device__ __forceinline__ float gelu_tanh(float v) {
    const float c = 0.7978845608028654f;
    float t = tanhf(c * (v + 0.044715f * v * v * v));
    return 0.5f * v * (1.0f + t);
}

// ---------------- cvt + bucket + worklist (one kernel) -------------------------
// Streaming blocks: fp32->fp16 for x, keys, values; zero-init out.
// Trailing block: zero counts, bucket all pairs, build dense tile worklist.
__device__ __forceinline__ uint32_t pack_h2(float a, float b) {
    __half2 h = __floats2half2_rn(a, b);
    return *reinterpret_cast<uint32_t*>(&h);
}
__global__ void cvt_all_kernel(const float* __restrict__ x,
                               const float* __restrict__ keys,
                               const float* __restrict__ values,
                               float* __restrict__ out,
                               const int* __restrict__ eidx) {
    if (blockIdx.x == gridDim.x - 1) {
        if (threadIdx.x == 0) {
#pragma unroll
            for (int e = 0; e < EE; e++) g_cnt[e] = 0;
        }
        __syncthreads();
#pragma unroll
        for (int s = 0; s < NPAIR / 512; s++) {
            int p = threadIdx.x + s * 512;
            int token = p / KK;
            int e = eidx[p];
            int pos = atomicAdd(&g_cnt[e], 1);
            g_tok [e * MAXR + pos] = token;
            g_pair[e * MAXR + pos] = p;
        }
        __syncthreads();
        if (threadIdx.x == 0) {
            int nt = 0;
#pragma unroll
            for (int e = 0; e < EE; e++) {
                int tiles = (g_cnt[e] + 127) >> 7;
                for (int t = 0; t < tiles; t++) g_tiles[nt++] = (e << 16) | t;
            }
            g_ntiles = nt;
        }
        return;
    }

    const int XN8 = BB * SS * DD / 8;
    const int KN8 = EE * HH * DD / 8;
    const int VN8 = EE * DD * HH / 8;
    const int ON8 = BB * SS * DD / 8;
    int i = blockIdx.x * blockDim.x + threadIdx.x;
    const float4* src; __half* dst; int j;
    if (i < XN8)                  { src = (const float4*)x;      dst = g_xh; j = i; }
    else if (i < XN8+KN8)         { src = (const float4*)keys;   dst = g_kh; j = i - XN8; }
    else if (i < XN8+KN8+VN8)     { src = (const float4*)values; dst = g_vh; j = i - XN8 - KN8; }
    else if (i < XN8+KN8+VN8+ON8) {
        int k = i - XN8 - KN8 - VN8;
        float4 z = make_float4(0.f, 0.f, 0.f, 0.f);
        reinterpret_cast<float4*>(out)[2*k]   = z;
        reinterpret_cast<float4*>(out)[2*k+1] = z;
        return;
    } else return;
    float4 v0 = __ldcs(src + 2*j);
    float4 v1 = __ldcs(src + 2*j + 1);
    uint4 o;
    o.x = pack_h2(v0.x, v0.y);
    o.y = pack_h2(v0.z, v0.w);
    o.z = pack_h2(v1.x, v1.y);
    o.w = pack_h2(v1.z, v1.w);
    reinterpret_cast<uint4*>(dst)[j] = o;
}

// ================= GEMM1: 8-warp, 256 threads, warp tile 32x64 ================
// hidden[pair] = gelu(x[token] @ keys[e]^T), fp16 out. Dense tile worklist.
#define A_TILE_B 16384
#define B_TILE_B 16384
#define STAGE_B  (A_TILE_B + B_TILE_B) // 32 KB
#define NSTAGE   3
#define SMEM_REQ (NSTAGE * STAGE_B)    // 96 KB

__global__ void __launch_bounds__(256, 2) moe_gemm1_kernel() {
    const int tid = threadIdx.x;

    if (blockIdx.y >= g_ntiles) return;
    const int ent  = g_tiles[blockIdx.y];
    const int e    = ent >> 16;
    const int row0 = (ent & 0xFFFF) * 128;
    const int n_rows = g_cnt[e];
    const int col0 = blockIdx.x * 128;

    const int* gat = g_tok  + e * MAXR;
    const int* pr  = g_pair + e * MAXR;
    const __half* A = g_xh;
    const __half* B = g_kh + (size_t)e * HH * DD;

    extern __shared__ char smem_dyn[];
    const uint32_t smB = smem_u32(smem_dyn);

    const int wid  = tid >> 5, lane = tid & 31;
    const int wm   = wid & 3;
    const int wn   = wid >> 2;

    const int c8    = tid & 7;
    const int rbase = tid >> 3;        // 0..31
    bool aok[4]; int aid[4]; uint32_t adst[4];
    int brow[4];  uint32_t bdst[4];
#pragma unroll
    for (int s = 0; s < 4; s++) {
        int r = rbase + 32 * s;
        uint32_t sw = sw128((uint32_t)(r * 128 + c8 * 16));
        adst[s] = sw;
        bdst[s] = A_TILE_B + sw;
        int grow = row0 + r;
        aok[s] = grow < n_rows;
        aid[s] = aok[s] ? gat[grow] : 0;
        brow[s] = col0 + r;
    }

    auto issue = [&](int stage, int buf) {
        size_t k0 = (size_t)stage * 64 + c8 * 8;
        uint32_t b = smB + (uint32_t)buf * STAGE_B;
#pragma unroll
        for (int s = 0; s < 4; s++)
            cp_async16(b + adst[s], A + (size_t)aid[s] * DD + k0, aok[s]);
#pragma unroll
        for (int s = 0; s < 4; s++)
            cp_async16(b + bdst[s], B + (size_t)brow[s] * DD + k0, true);
        CP_COMMIT();
    };

    float acc[2][8][4];
#pragma unroll
    for (int mt = 0; mt < 2; mt++)
#pragma unroll
        for (int nt = 0; nt < 8; nt++)
#pragma unroll
            for (int r = 0; r < 4; r++) acc[mt][nt][r] = 0.0f;

    const int aRowL  = wm * 32 + (lane & 15);
    const int aKHalf = (lane >> 4) * 16;
    const int bRowL  = wn * 64 + ((lane >> 4) << 3) + (lane & 7);
    const int bKHalf = ((lane >> 3) & 1) * 16;

    uint32_t ah[2][2][4], bh[2][4][4];

    auto load_frags = [&](int fb, uint32_t sA, uint32_t sB, int ks) {
        const int kb = ks * 32;
#pragma unroll
        for (int mt = 0; mt < 2; mt++)
            ldsm4(ah[fb][mt], sA + sw128((uint32_t)((aRowL + mt*16) * 128 + kb + aKHalf)));
#pragma unroll
        for (int ng = 0; ng < 4; ng++)
            ldsm4(bh[fb][ng], sB + sw128((uint32_t)((bRowL + ng*16) * 128 + kb + bKHalf)));
    };
    auto do_mma = [&](int fb) {
#pragma unroll
        for (int mt = 0; mt < 2; mt++)
#pragma unroll
            for (int nt = 0; nt < 8; nt++) {
                const int ng = nt >> 1, h = (nt & 1) * 2;
                mma16816(acc[mt][nt], ah[fb][mt], bh[fb][ng][h], bh[fb][ng][h+1]);
            }
    };

    const int NS = DD / 64;
    issue(0, 0);
    issue(1, 1);

    for (int i = 0; i < NS; i++) {
        const int buf = i % NSTAGE;
        if (i + 1 < NS) { CP_WAIT(1); } else { CP_WAIT(0); }
        __syncthreads();
        if (i + 2 < NS) issue(i + 2, (i + 2) % NSTAGE);

        const uint32_t bb = smB + (uint32_t)buf * STAGE_B;
        const uint32_t sA = bb, sB = bb + A_TILE_B;

        load_frags(0, sA, sB, 0);
#pragma unroll
        for (int ks = 0; ks < 4; ks++) {
            if (ks < 3) load_frags((ks + 1) & 1, sA, sB, ks + 1);
            do_mma(ks & 1);
        }
    }

    int prid[2][2];
#pragma unroll
    for (int mt = 0; mt < 2; mt++)
#pragma unroll
        for (int hf = 0; hf < 2; hf++) {
            int grow = row0 + wm*32 + mt*16 + (lane >> 2) + hf*8;
            prid[mt][hf] = (grow < n_rows) ? pr[grow] : -1;
        }

#pragma unroll
    for (int mt = 0; mt < 2; mt++)
#pragma unroll
        for (int hf = 0; hf < 2; hf++) {
            const int pid = prid[mt][hf];
            if (pid < 0) continue;
#pragma unroll
            for (int nt = 0; nt < 8; nt++) {
                const int colg = col0 + wn*64 + nt*8 + (lane & 3)*2;
                float v0 = gelu_tanh(acc[mt][nt][hf*2 + 0]);
                float v1 = gelu_tanh(acc[mt][nt][hf*2 + 1]);
                *reinterpret_cast<__half2*>(g_hid + (size_t)pid * HH + colg) =
                    __floats2half2_rn(v0, v1);
            }
        }
}

// ================= GEMM2: 4-warp, 128 threads, warp tile 64x64 ================
// out[token] += ew[pair] * (hidden[pair] @ values[e]^T), atomicAdd epilogue.
__global__ void __launch_bounds__(128, 2) moe_gemm2_kernel(const float* __restrict__ ew,
                                                           float* __restrict__ out) {
    const int tid = threadIdx.x;

    if (blockIdx.y >= g_ntiles) return;
    const int ent  = g_tiles[blockIdx.y];
    const int e    = ent >> 16;
    const int row0 = (ent & 0xFFFF) * 128;
    const int n_rows = g_cnt[e];
    const int col0 = blockIdx.x * 128;

    const int* pr  = g_pair + e * MAXR;
    const __half* A = g_hid;
    const __half* B = g_vh + (size_t)e * DD * HH;

    extern __shared__ char smem_dyn[];
    const uint32_t smB = smem_u32(smem_dyn);

    const int wid  = tid >> 5, lane = tid & 31;
    const int wm   = wid & 1;
    const int wn   = wid >> 1;

    const int c8    = tid & 7;
    const int rbase = tid >> 3;        // 0..15
    bool aok[8]; int aid[8]; uint32_t adst[8];
    int brow[8];  uint32_t bdst[8];
#pragma unroll
    for (int s = 0; s < 8; s++) {
        int r = rbase + 16 * s;
        uint32_t sw = sw128((uint32_t)(r * 128 + c8 * 16));
        adst[s] = sw;
        bdst[s] = A_TILE_B + sw;
        int grow = row0 + r;
        aok[s] = grow < n_rows;
        aid[s] = aok[s] ? pr[grow] : 0;
        brow[s] = col0 + r;
    }

    auto issue = [&](int stage, int buf) {
        size_t k0 = (size_t)stage * 64 + c8 * 8;
        uint32_t b = smB + (uint32_t)buf * STAGE_B;
#pragma unroll
        for (int s = 0; s < 8; s++)
            cp_async16(b + adst[s], A + (size_t)aid[s] * HH + k0, aok[s]);
#pragma unroll
        for (int s = 0; s < 8; s++)
            cp_async16(b + bdst[s], B + (size_t)brow[s] * HH + k0, true);
        CP_COMMIT();
    };

    float acc[4][8][4];
#pragma unroll
    for (int mt = 0; mt < 4; mt++)
#pragma unroll
        for (int nt = 0; nt < 8; nt++)
#pragma unroll
            for (int r = 0; r < 4; r++) acc[mt][nt][r] = 0.0f;

    const int aRowL  = wm * 64 + (lane & 15);
    const int aKHalf = (lane >> 4) * 16;
    const int bRowL  = wn * 64 + ((lane >> 4) << 3) + (lane & 7);
    const int bKHalf = ((lane >> 3) & 1) * 16;

    uint32_t ah[2][4][4], bh[2][4][4];

    auto load_frags = [&](int fb, uint32_t sA, uint32_t sB, int ks) {
        const int kb = ks * 32;
#pragma unroll
        for (int mt = 0; mt < 4; mt++)
            ldsm4(ah[fb][mt], sA + sw128((uint32_t)((aRowL + mt*16) * 128 + kb + aKHalf)));
#pragma unroll
        for (int ng = 0; ng < 4; ng++)
            ldsm4(bh[fb][ng], sB + sw128((uint32_t)((bRowL + ng*16) * 128 + kb + bKHalf)));
    };
    auto do_mma = [&](int fb) {
#pragma unroll
        for (int mt = 0; mt < 4; mt++)
#pragma unroll
            for (int nt = 0; nt < 8; nt++) {
                const int ng = nt >> 1, h = (nt & 1) * 2;
                mma16816(acc[mt][nt], ah[fb][mt], bh[fb][ng][h], bh[fb][ng][h+1]);
            }
    };

    const int NS = HH / 64;
    issue(0, 0);
    issue(1, 1);

    for (int i = 0; i < NS; i++) {
        const int buf = i % NSTAGE;
        if (i + 1 < NS) { CP_WAIT(1); } else { CP_WAIT(0); }
        __syncthreads();
        if (i + 2 < NS) issue(i + 2, (i + 2) % NSTAGE);

        const uint32_t bb = smB + (uint32_t)buf * STAGE_B;
        const uint32_t sA = bb, sB = bb + A_TILE_B;

        load_frags(0, sA, sB, 0);
#pragma unroll
        for (int ks = 0; ks < 4; ks++) {
            if (ks < 3) load_frags((ks + 1) & 1, sA, sB, ks + 1);
            do_mma(ks & 1);
        }
    }

    int   prid[4][2];
    float wgt [4][2];
#pragma unroll
    for (int mt = 0; mt < 4; mt++)
#pragma unroll
        for (int hf = 0; hf < 2; hf++) {
            int grow = row0 + wm*64 + mt*16 + (lane >> 2) + hf*8;
            prid[mt][hf] = (grow < n_rows) ? pr[grow] : -1;
            wgt [mt][hf] = (prid[mt][hf] >= 0) ? ew[prid[mt][hf]] : 1.0f;
        }

#pragma unroll
    for (int mt = 0; mt < 4; mt++)
#pragma unroll
        for (int hf = 0; hf < 2; hf++) {
            const int pid = prid[mt][hf];
            if (pid < 0) continue;
            const float w = wgt[mt][hf];
#pragma unroll
            for (int nt = 0; nt < 8; nt++) {
                const int colg = col0 + wn*64 + nt*8 + (lane & 3)*2;
                // out[token, colg] += w * v ; exactly 2 commutative adds per
                // element across the kernel -> deterministic.
                float* dst = out + (size_t)(pid >> 1) * DD + colg;
                atomicAdd(dst + 0, w * acc[mt][nt][hf*2 + 0]);
                atomicAdd(dst + 1, w * acc[mt][nt][hf*2 + 1]);
            }
        }
}

// ---------------- entry point ---------------------------------------------------
extern "C" void kernel_launch(void* const* d_in, const int* in_sizes, int n_in,
                              void* d_out, int out_size) {
    const float* x      = (const float*)d_in[0];   // [B,S,D]
    const float* keys   = (const float*)d_in[1];   // [E,H,D]
    const float* values = (const float*)d_in[2];   // [E,D,H]
    const int*   eidx   = (const int*)  d_in[3];   // [B,S,K]
    const float* ew     = (const float*)d_in[4];   // [B,S,K]
    float* out = (float*)d_out;                    // [B,S,D]

    cudaFuncSetAttribute((const void*)moe_gemm1_kernel,
                         cudaFuncAttributeMaxDynamicSharedMemorySize, SMEM_REQ);
    cudaFuncSetAttribute((const void*)moe_gemm2_kernel,
                         cudaFuncAttributeMaxDynamicSharedMemorySize, SMEM_REQ);

    const int TOT8 = (BB*SS*DD + EE*HH*DD + EE*DD*HH + BB*SS*DD) / 8;
    const int nblk = (TOT8 + 511) / 512 + 1;   // +1 trailing bucket/worklist block
    cvt_all_kernel<<<nblk, 512>>>(x, keys, values, out, eidx);

    dim3 g1(HH / 128, NTILE_MAX, 1);   // (16, 39)
    moe_gemm1_kernel<<<g1, 256, SMEM_REQ>>>();

    dim3 g2(DD / 128, NTILE_MAX, 1);   // (8, 39)
    moe_gemm2_kernel<<<g2, 128, SMEM_REQ>>>(ew, out);
}